// round 3
// baseline (speedup 1.0000x reference)
#include <cuda_runtime.h>
#include <math.h>

// Problem constants
#define BB   256
#define TT   512
#define DD   1024
#define HH   1024
#define MTOT (BB * TT)          // 131072 rows of the input-projection GEMM
#define BH   (BB * HH)          // 262144 elements in one h / one x_proj time-slice
#define WSTRIDE (DD + HH)       // 2048, row stride of W

// ---------------------------------------------------------------------------
// Scratch (device globals: allocation-free rule)
// ---------------------------------------------------------------------------
__device__ float g_xproj[134217728];          // [T][B][H]  512 MB
__device__ float g_h[2][BH];                  // double-buffered hidden state
__device__ unsigned g_bar;                    // grid barrier counter (reset each launch)

typedef unsigned long long ull;

// Packed fp32x2 FMA (Blackwell FFMA2; PTX-only path, exact fp32 numerics)
__device__ __forceinline__ void fma2(ull &d, ull a, ull b) {
    asm("fma.rn.f32x2 %0, %1, %2, %0;" : "+l"(d) : "l"(a), "l"(b));
}
__device__ __forceinline__ ull dup2(float a) {
    ull r; asm("mov.b64 %0, {%1, %1};" : "=l"(r) : "f"(a)); return r;
}
__device__ __forceinline__ ull pack2(float lo, float hi) {
    ull r; asm("mov.b64 %0, {%1, %2};" : "=l"(r) : "f"(lo), "f"(hi)); return r;
}
__device__ __forceinline__ float2 unpack2(ull v) {
    float2 r; asm("mov.b64 {%0, %1}, %2;" : "=f"(r.x), "=f"(r.y) : "l"(v)); return r;
}

// ---------------------------------------------------------------------------
// Kernel 1: x_proj[(t*B + b), :] = xs[(b*T + t), :] @ Wx^T + bias
// Tiles: BM=128, BN=64, BK=16. 128 threads, 8x8 microtile (as 8x4 f32x2).
// ---------------------------------------------------------------------------
#define XP_BM 128
#define XP_BN 64
#define XP_BK 16
#define XP_LDA 132
#define XP_LDB 68

__global__ void __launch_bounds__(128) xproj_gemm(const float* __restrict__ xs,
                                                  const float* __restrict__ W,
                                                  const float* __restrict__ bias) {
    __shared__ __align__(16) float As[XP_BK][XP_LDA];
    __shared__ __align__(16) float Bs[XP_BK][XP_LDB];

    const int tid = threadIdx.x;
    const int tx = tid & 7;
    const int ty = tid >> 3;
    const int m0 = blockIdx.y * XP_BM;
    const int n0 = blockIdx.x * XP_BN;

    ull acc[8][4];
#pragma unroll
    for (int i = 0; i < 8; i++)
#pragma unroll
        for (int j = 0; j < 4; j++) acc[i][j] = 0ull;

    const float* Aptr = xs + (size_t)m0 * DD;
    const float* Bptr = W + (size_t)n0 * WSTRIDE;     // Wx part: cols [0, DD)

    for (int kt = 0; kt < DD; kt += XP_BK) {
#pragma unroll
        for (int l = 0; l < 4; l++) {
            int j = tid + l * 128;
            int row = j >> 2, c4 = (j & 3) * 4;
            float4 v = *reinterpret_cast<const float4*>(Aptr + (size_t)row * DD + kt + c4);
            As[c4 + 0][row] = v.x; As[c4 + 1][row] = v.y;
            As[c4 + 2][row] = v.z; As[c4 + 3][row] = v.w;
        }
#pragma unroll
        for (int l = 0; l < 2; l++) {
            int j = tid + l * 128;
            int row = j >> 2, c4 = (j & 3) * 4;
            float4 v = *reinterpret_cast<const float4*>(Bptr + (size_t)row * WSTRIDE + kt + c4);
            Bs[c4 + 0][row] = v.x; Bs[c4 + 1][row] = v.y;
            Bs[c4 + 2][row] = v.z; Bs[c4 + 3][row] = v.w;
        }
        __syncthreads();
#pragma unroll
        for (int k = 0; k < XP_BK; k++) {
            float4 a0 = *reinterpret_cast<const float4*>(&As[k][ty * 8]);
            float4 a1 = *reinterpret_cast<const float4*>(&As[k][ty * 8 + 4]);
            ulonglong2 b0 = *reinterpret_cast<const ulonglong2*>(&Bs[k][tx * 8]);
            ulonglong2 b1 = *reinterpret_cast<const ulonglong2*>(&Bs[k][tx * 8 + 4]);
            float av[8] = {a0.x, a0.y, a0.z, a0.w, a1.x, a1.y, a1.z, a1.w};
            ull   bv[4] = {b0.x, b0.y, b1.x, b1.y};
#pragma unroll
            for (int i = 0; i < 8; i++) {
                ull ad = dup2(av[i]);
                fma2(acc[i][0], ad, bv[0]);
                fma2(acc[i][1], ad, bv[1]);
                fma2(acc[i][2], ad, bv[2]);
                fma2(acc[i][3], ad, bv[3]);
            }
        }
        __syncthreads();
    }

    const int nb = n0 + tx * 8;
    float4 bias0 = *reinterpret_cast<const float4*>(bias + nb);
    float4 bias1 = *reinterpret_cast<const float4*>(bias + nb + 4);
#pragma unroll
    for (int i = 0; i < 8; i++) {
        int mg = m0 + ty * 8 + i;
        int b_idx = mg >> 9;    // / T
        int t     = mg & 511;   // % T
        float* out = g_xproj + ((size_t)t * BB + b_idx) * HH + nb;
        float2 v0 = unpack2(acc[i][0]);
        float2 v1 = unpack2(acc[i][1]);
        float2 v2 = unpack2(acc[i][2]);
        float2 v3 = unpack2(acc[i][3]);
        float4 o0 = make_float4(v0.x + bias0.x, v0.y + bias0.y, v1.x + bias0.z, v1.y + bias0.w);
        float4 o1 = make_float4(v2.x + bias1.x, v2.y + bias1.y, v3.x + bias1.z, v3.y + bias1.w);
        *reinterpret_cast<float4*>(out)     = o0;
        *reinterpret_cast<float4*>(out + 4) = o1;
    }
}

// ---------------------------------------------------------------------------
// Kernel 2: persistent recurrence. 128 CTAs x 128 threads, 1 CTA/SM.
// CTA (mi, ni) owns h tile rows [mi*64, +64), cols [ni*32, +32).
// Wh slice (32 cols x 1024 k) lives in smem for all 512 steps, packed as
// f32x2 column pairs: Whp[np][k] = (Wh[n0+2np][k], Wh[n0+2np+1][k]).
// Per step: C[64x32] = h[64x1024] * Whp^T, then tanh(xp + C).
// ---------------------------------------------------------------------------
#define RN_CTAS 128
#define RN_THREADS 128
#define RN_KC 32                 // k-chunk staged per buffer
#define RN_LDA 65                // padded row stride of staged A (conflict-free)
#define RN_ABUF (RN_KC * RN_LDA) // floats per A buffer
#define RN_SMEM (16 * 1024 * 8 + 2 * RN_ABUF * 4)   // 131072 + 16640 = 147712 B

__device__ __forceinline__ void grid_sync(unsigned target) {
    __syncthreads();
    if (threadIdx.x == 0) {
        __threadfence();                       // release prior writes
        atomicAdd(&g_bar, 1u);
        while (*((volatile unsigned*)&g_bar) < target) { }
        __threadfence();                       // acquire
    }
    __syncthreads();
}

__global__ void __launch_bounds__(RN_THREADS, 1) recur_persistent(
        const float* __restrict__ W, float* __restrict__ out, int copies) {
    extern __shared__ __align__(16) float smem[];
    ull*   Whp = reinterpret_cast<ull*>(smem);          // [16][1024]
    float* As  = smem + 16 * 1024 * 2;                  // [2][RN_KC][RN_LDA]

    const int tid  = threadIdx.x;
    const int cta  = blockIdx.x;
    const int mi   = cta & 3;           // 4 M-splits
    const int ni   = cta >> 2;          // 32 N-splits
    const int m0   = mi * 64;
    const int n0   = ni * 32;
    const int lane = tid & 31;
    const int wid  = tid >> 5;
    const int wm   = wid & 1;           // warp M half
    const int wn   = wid >> 1;          // warp N half
    const int lrow = wm * 32 + lane;    // row within CTA tile (0..63)
    const int row  = m0 + lrow;         // global batch row
    const int npb  = wn * 8;            // first col-pair this thread owns
    const int nc0  = n0 + wn * 16;      // first global col this thread owns

    // ---- Load resident Wh slice, packed as column pairs -------------------
    for (int i = tid; i < 16 * 1024; i += RN_THREADS) {
        int np = i >> 10, k = i & 1023;
        float lo = W[(size_t)(n0 + 2 * np)     * WSTRIDE + DD + k];
        float hi = W[(size_t)(n0 + 2 * np + 1) * WSTRIDE + DD + k];
        Whp[(size_t)np * 1024 + k] = pack2(lo, hi);
    }

    // ---- Step 0: h0 = 0  ->  h = tanh(x_proj[0]) --------------------------
    {
        const float4* xp = reinterpret_cast<const float4*>(
            g_xproj + (size_t)row * HH + nc0);
        float4* hd = reinterpret_cast<float4*>(g_h[0] + (size_t)row * HH + nc0);
#pragma unroll
        for (int q = 0; q < 4; q++) {
            float4 v = __ldcs(xp + q);
            hd[q] = make_float4(tanhf(v.x), tanhf(v.y), tanhf(v.z), tanhf(v.w));
        }
    }
    grid_sync(1u * RN_CTAS);

    // staging thread mapping: 2 threads per row, 16 k each
    const int sr = tid >> 1;               // 0..63
    const int sk = (tid & 1) * 16;

    // ---- Steps 1..511 -----------------------------------------------------
    for (int t = 1; t < TT; t++) {
        const float* hsrc = g_h[(t - 1) & 1] + (size_t)m0 * HH;

        ull acc[8];
#pragma unroll
        for (int j = 0; j < 8; j++) acc[j] = 0ull;

        // prologue: stage chunk 0 into buffer 0
        {
            const float4* p = reinterpret_cast<const float4*>(hsrc + (size_t)sr * HH + sk);
            float4 v0 = __ldcg(p + 0), v1 = __ldcg(p + 1), v2 = __ldcg(p + 2), v3 = __ldcg(p + 3);
            float* dst = As;
            dst[(sk + 0) * RN_LDA + sr] = v0.x;  dst[(sk + 1) * RN_LDA + sr] = v0.y;
            dst[(sk + 2) * RN_LDA + sr] = v0.z;  dst[(sk + 3) * RN_LDA + sr] = v0.w;
            dst[(sk + 4) * RN_LDA + sr] = v1.x;  dst[(sk + 5) * RN_LDA + sr] = v1.y;
            dst[(sk + 6) * RN_LDA + sr] = v1.z;  dst[(sk + 7) * RN_LDA + sr] = v1.w;
            dst[(sk + 8) * RN_LDA + sr] = v2.x;  dst[(sk + 9) * RN_LDA + sr] = v2.y;
            dst[(sk +10) * RN_LDA + sr] = v2.z;  dst[(sk +11) * RN_LDA + sr] = v2.w;
            dst[(sk +12) * RN_LDA + sr] = v3.x;  dst[(sk +13) * RN_LDA + sr] = v3.y;
            dst[(sk +14) * RN_LDA + sr] = v3.z;  dst[(sk +15) * RN_LDA + sr] = v3.w;
        }

#pragma unroll 1
        for (int c = 0; c < HH / RN_KC; c++) {
            __syncthreads();   // staged buffer c ready; buffer c-1 compute done
            if (c + 1 < HH / RN_KC) {
                int kc = (c + 1) * RN_KC;
                const float4* p = reinterpret_cast<const float4*>(hsrc + (size_t)sr * HH + kc + sk);
                float4 v0 = __ldcg(p + 0), v1 = __ldcg(p + 1), v2 = __ldcg(p + 2), v3 = __ldcg(p + 3);
                float* dst = As + ((c + 1) & 1) * RN_ABUF;
                dst[(sk + 0) * RN_LDA + sr] = v0.x;  dst[(sk + 1) * RN_LDA + sr] = v0.y;
                dst[(sk + 2) * RN_LDA + sr] = v0.z;  dst[(sk + 3) * RN_LDA + sr] = v0.w;
                dst[(sk + 4) * RN_LDA + sr] = v1.x;  dst[(sk + 5) * RN_LDA + sr] = v1.y;
                dst[(sk + 6) * RN_LDA + sr] = v1.z;  dst[(sk + 7) * RN_LDA + sr] = v1.w;
                dst[(sk + 8) * RN_LDA + sr] = v2.x;  dst[(sk + 9) * RN_LDA + sr] = v2.y;
                dst[(sk +10) * RN_LDA + sr] = v2.z;  dst[(sk +11) * RN_LDA + sr] = v2.w;
                dst[(sk +12) * RN_LDA + sr] = v3.x;  dst[(sk +13) * RN_LDA + sr] = v3.y;
                dst[(sk +14) * RN_LDA + sr] = v3.z;  dst[(sk +15) * RN_LDA + sr] = v3.w;
            }
            const float* Ab = As + (c & 1) * RN_ABUF;
            const ull*   Bb = Whp + (size_t)npb * 1024 + c * RN_KC;
#pragma unroll 8
            for (int kk = 0; kk < RN_KC; kk++) {
                ull ad = dup2(Ab[kk * RN_LDA + lrow]);
                fma2(acc[0], ad, Bb[0 * 1024 + kk]);
                fma2(acc[1], ad, Bb[1 * 1024 + kk]);
                fma2(acc[2], ad, Bb[2 * 1024 + kk]);
                fma2(acc[3], ad, Bb[3 * 1024 + kk]);
                fma2(acc[4], ad, Bb[4 * 1024 + kk]);
                fma2(acc[5], ad, Bb[5 * 1024 + kk]);
                fma2(acc[6], ad, Bb[6 * 1024 + kk]);
                fma2(acc[7], ad, Bb[7 * 1024 + kk]);
            }
        }

        // epilogue: out_val = tanh(xp + acc)
        {
            const float4* xp = reinterpret_cast<const float4*>(
                g_xproj + (size_t)t * BH + (size_t)row * HH + nc0);
            if (t == TT - 1) {
#pragma unroll
                for (int q = 0; q < 4; q++) {
                    float2 e0 = unpack2(acc[2 * q]);
                    float2 e1 = unpack2(acc[2 * q + 1]);
                    float4 x = __ldcs(xp + q);
                    float4 o = make_float4(tanhf(e0.x + x.x), tanhf(e0.y + x.y),
                                           tanhf(e1.x + x.z), tanhf(e1.y + x.w));
                    for (int cc = 0; cc < copies; cc++)
                        *reinterpret_cast<float4*>(out + (size_t)cc * BH +
                                                   (size_t)row * HH + nc0 + q * 4) = o;
                }
            } else {
                float4* hd = reinterpret_cast<float4*>(g_h[t & 1] + (size_t)row * HH + nc0);
#pragma unroll
                for (int q = 0; q < 4; q++) {
                    float2 e0 = unpack2(acc[2 * q]);
                    float2 e1 = unpack2(acc[2 * q + 1]);
                    float4 x = __ldcs(xp + q);
                    hd[q] = make_float4(tanhf(e0.x + x.x), tanhf(e0.y + x.y),
                                        tanhf(e1.x + x.z), tanhf(e1.y + x.w));
                }
            }
        }
        grid_sync((unsigned)(t + 1) * RN_CTAS);
    }

    // reset barrier for the next graph replay (all CTAs have passed sync 512)
    if (cta == 0 && tid == 0) atomicExch(&g_bar, 0u);
}

// ---------------------------------------------------------------------------
extern "C" void kernel_launch(void* const* d_in, const int* in_sizes, int n_in,
                              void* d_out, int out_size) {
    const float* xs = nullptr; const float* W = nullptr; const float* b = nullptr;
    for (int i = 0; i < n_in; i++) {
        if (in_sizes[i] == MTOT * DD)            xs = (const float*)d_in[i];
        else if (in_sizes[i] == HH * WSTRIDE)    W  = (const float*)d_in[i];
        else if (in_sizes[i] == HH)              b  = (const float*)d_in[i];
    }
    float* out = (float*)d_out;
    int copies = out_size / BH;
    if (copies < 1) copies = 1;

    static bool configured = false;
    if (!configured) {
        cudaFuncSetAttribute(recur_persistent,
                             cudaFuncAttributeMaxDynamicSharedMemorySize, RN_SMEM);
        configured = true;
    }

    // 1. Input projection GEMM (writes x_proj in [T][B][H] layout, bias fused)
    xproj_gemm<<<dim3(HH / XP_BN, MTOT / XP_BM), 128>>>(xs, W, b);

    // 2. Entire 512-step recurrence in one persistent kernel (incl. output)
    recur_persistent<<<RN_CTAS, RN_THREADS, RN_SMEM>>>(W, out, copies);
}

// round 6
// speedup vs baseline: 1.0110x; 1.0110x over previous
#include <cuda_runtime.h>
#include <math.h>

// Problem constants
#define BB   256
#define TT   512
#define DD   1024
#define HH   1024
#define MTOT (BB * TT)
#define BH   (BB * HH)
#define WSTRIDE (DD + HH)

// ---------------------------------------------------------------------------
// Scratch (device globals: allocation-free rule)
// ---------------------------------------------------------------------------
__device__ float g_xproj[134217728];          // [T][B][H]  512 MB
__device__ float g_h[2][BH];                  // double-buffered hidden state
__device__ unsigned g_barM[8 * 32];           // 8 band barrier counters, 128B apart

typedef unsigned long long ull;

__device__ __forceinline__ void fma2(ull &d, ull a, ull b) {
    asm("fma.rn.f32x2 %0, %1, %2, %0;" : "+l"(d) : "l"(a), "l"(b));
}
__device__ __forceinline__ ull add2(ull a, ull b) {
    ull r; asm("add.rn.f32x2 %0, %1, %2;" : "=l"(r) : "l"(a), "l"(b)); return r;
}
__device__ __forceinline__ ull dup2(float a) {
    ull r; asm("mov.b64 %0, {%1, %1};" : "=l"(r) : "f"(a)); return r;
}
__device__ __forceinline__ float2 unpack2(ull v) {
    float2 r; asm("mov.b64 {%0, %1}, %2;" : "=f"(r.x), "=f"(r.y) : "l"(v)); return r;
}

// ---------------------------------------------------------------------------
// Kernel 1: x_proj[(t*B + b), :] = xs[(b*T + t), :] @ Wx^T + bias
// ---------------------------------------------------------------------------
#define XP_BM 128
#define XP_BN 64
#define XP_BK 16
#define XP_LDA 132
#define XP_LDB 68

__global__ void __launch_bounds__(128) xproj_gemm(const float* __restrict__ xs,
                                                  const float* __restrict__ W,
                                                  const float* __restrict__ bias) {
    __shared__ __align__(16) float As[XP_BK][XP_LDA];
    __shared__ __align__(16) float Bs[XP_BK][XP_LDB];

    const int tid = threadIdx.x;
    const int tx = tid & 7;
    const int ty = tid >> 3;
    const int m0 = blockIdx.y * XP_BM;
    const int n0 = blockIdx.x * XP_BN;

    ull acc[8][4];
#pragma unroll
    for (int i = 0; i < 8; i++)
#pragma unroll
        for (int j = 0; j < 4; j++) acc[i][j] = 0ull;

    const float* Aptr = xs + (size_t)m0 * DD;
    const float* Bptr = W + (size_t)n0 * WSTRIDE;

    for (int kt = 0; kt < DD; kt += XP_BK) {
#pragma unroll
        for (int l = 0; l < 4; l++) {
            int j = tid + l * 128;
            int row = j >> 2, c4 = (j & 3) * 4;
            float4 v = *reinterpret_cast<const float4*>(Aptr + (size_t)row * DD + kt + c4);
            As[c4 + 0][row] = v.x; As[c4 + 1][row] = v.y;
            As[c4 + 2][row] = v.z; As[c4 + 3][row] = v.w;
        }
#pragma unroll
        for (int l = 0; l < 2; l++) {
            int j = tid + l * 128;
            int row = j >> 2, c4 = (j & 3) * 4;
            float4 v = *reinterpret_cast<const float4*>(Bptr + (size_t)row * WSTRIDE + kt + c4);
            Bs[c4 + 0][row] = v.x; Bs[c4 + 1][row] = v.y;
            Bs[c4 + 2][row] = v.z; Bs[c4 + 3][row] = v.w;
        }
        __syncthreads();
#pragma unroll
        for (int k = 0; k < XP_BK; k++) {
            float4 a0 = *reinterpret_cast<const float4*>(&As[k][ty * 8]);
            float4 a1 = *reinterpret_cast<const float4*>(&As[k][ty * 8 + 4]);
            ulonglong2 b0 = *reinterpret_cast<const ulonglong2*>(&Bs[k][tx * 8]);
            ulonglong2 b1 = *reinterpret_cast<const ulonglong2*>(&Bs[k][tx * 8 + 4]);
            float av[8] = {a0.x, a0.y, a0.z, a0.w, a1.x, a1.y, a1.z, a1.w};
            ull   bv[4] = {b0.x, b0.y, b1.x, b1.y};
#pragma unroll
            for (int i = 0; i < 8; i++) {
                ull ad = dup2(av[i]);
                fma2(acc[i][0], ad, bv[0]);
                fma2(acc[i][1], ad, bv[1]);
                fma2(acc[i][2], ad, bv[2]);
                fma2(acc[i][3], ad, bv[3]);
            }
        }
        __syncthreads();
    }

    const int nb = n0 + tx * 8;
    float4 bias0 = *reinterpret_cast<const float4*>(bias + nb);
    float4 bias1 = *reinterpret_cast<const float4*>(bias + nb + 4);
#pragma unroll
    for (int i = 0; i < 8; i++) {
        int mg = m0 + ty * 8 + i;
        int b_idx = mg >> 9;
        int t     = mg & 511;
        float* outp = g_xproj + ((size_t)t * BB + b_idx) * HH + nb;
        float2 v0 = unpack2(acc[i][0]);
        float2 v1 = unpack2(acc[i][1]);
        float2 v2 = unpack2(acc[i][2]);
        float2 v3 = unpack2(acc[i][3]);
        float4 o0 = make_float4(v0.x + bias0.x, v0.y + bias0.y, v1.x + bias0.z, v1.y + bias0.w);
        float4 o1 = make_float4(v2.x + bias1.x, v2.y + bias1.y, v3.x + bias1.z, v3.y + bias1.w);
        *reinterpret_cast<float4*>(outp)     = o0;
        *reinterpret_cast<float4*>(outp + 4) = o1;
    }
}

// ---------------------------------------------------------------------------
// Kernel 2: persistent recurrence v2 (hardened).
// Grid (16, 8) = 128 CTAs (1/SM). CTA (ni, mi): h tile rows [mi*32,+32),
// cols [ni*64,+64). 256 threads = 4 k-groups x 64; group g covers k in
// [g*256,(g+1)*256). Thread micro-tile 4 rows x 8 cols (4x4 f32x2).
// Double-buffered smem staging of h (A) and Wh (B), chunk KC=32.
// Band barrier: 16 CTAs sharing mi sync on g_barM[mi*32].
// ---------------------------------------------------------------------------
#define RN_KC   32
#define RN_LDA  36
#define RN_ABUF (RN_KC * RN_LDA)
#define RN_BBUF (RN_KC * 64)
#define RN_AS_TOTAL (4 * 2 * RN_ABUF)    // 9216 floats
#define RN_BS_TOTAL (4 * 2 * RN_BBUF)    // 16384 floats
#define RN_SMEM ((RN_AS_TOTAL + RN_BS_TOTAL) * 4)   // 102400 B

__device__ __forceinline__ void band_barrier(unsigned* ctr, unsigned target) {
    __syncthreads();
    if (threadIdx.x == 0) {
        __threadfence();
        atomicAdd(ctr, 1u);
        while (*((volatile unsigned*)ctr) < target) { __nanosleep(32); }
        __threadfence();
    }
    __syncthreads();
}

__global__ void __launch_bounds__(256, 1) recur_persistent(
        const float* __restrict__ W, float* __restrict__ out, int copies) {
    extern __shared__ __align__(16) float smem[];
    float* AsAll = smem;                    // [4][2][RN_KC][RN_LDA]
    float* BsAll = smem + RN_AS_TOTAL;      // [4][2][RN_KC][64]
    ull*   red   = reinterpret_cast<ull*>(smem + RN_AS_TOTAL);  // [4][1024] reuse

    const int tid = threadIdx.x;
    const int ni  = blockIdx.x;             // 0..15
    const int mi  = blockIdx.y;             // 0..7
    const int m0  = mi * 32;
    const int n0  = ni * 64;

    const int g   = tid >> 6;               // k-group 0..3
    const int gt  = tid & 63;
    const int ty  = gt >> 3;                // rows ty*4..+4
    const int tx  = gt & 7;                 // cols tx*8..+8
    const int kg  = g * 256;

    float* Asg = AsAll + g * (2 * RN_ABUF);
    float* Bsg = BsAll + g * (2 * RN_BBUF);

    const int a_row  = gt >> 1;
    const int a_kofs = (gt & 1) * 16;
    const int b_n    = gt;

    unsigned* ctr = &g_barM[mi * 32];

    const int p0    = tid * 4;
    const int o_row = p0 >> 5;
    const int o_c8  = (p0 & 31) * 2;
    const size_t o_off = (size_t)(m0 + o_row) * HH + n0 + o_c8;

    // ---- Step 0: h0 = 0  ->  h[0] = tanh(x_proj[0]) -----------------------
    {
        const float4* xp = reinterpret_cast<const float4*>(g_xproj + o_off);
        float4* hd = reinterpret_cast<float4*>(g_h[0] + o_off);
#pragma unroll
        for (int q = 0; q < 2; q++) {
            float4 v = __ldcs(xp + q);
            hd[q] = make_float4(tanhf(v.x), tanhf(v.y), tanhf(v.z), tanhf(v.w));
        }
    }

    const float* Wh = W + DD;

    // ---- Steps 1..511 -----------------------------------------------------
    for (int t = 1; t < TT; t++) {
        band_barrier(ctr, (unsigned)t * 16u);

        const float* hsrc = g_h[(t - 1) & 1];

        ull acc[4][4];
#pragma unroll
        for (int i = 0; i < 4; i++)
#pragma unroll
            for (int j = 0; j < 4; j++) acc[i][j] = 0ull;

        // prologue: stage chunk 0 into buffer 0
        {
            const int kb = kg;
            const float4* ap = reinterpret_cast<const float4*>(
                hsrc + (size_t)(m0 + a_row) * HH + kb + a_kofs);
            float* Ad = Asg;
#pragma unroll
            for (int l = 0; l < 4; l++) {
                float4 v = __ldcg(ap + l);
                int kk = a_kofs + l * 4;
                Ad[(kk + 0) * RN_LDA + a_row] = v.x;
                Ad[(kk + 1) * RN_LDA + a_row] = v.y;
                Ad[(kk + 2) * RN_LDA + a_row] = v.z;
                Ad[(kk + 3) * RN_LDA + a_row] = v.w;
            }
            const float4* bp = reinterpret_cast<const float4*>(
                Wh + (size_t)(n0 + b_n) * WSTRIDE + kb);
            float* Bd = Bsg;
#pragma unroll
            for (int l = 0; l < 8; l++) {
                float4 v = bp[l];
                int kk = l * 4;
                Bd[(kk + 0) * 64 + b_n] = v.x;
                Bd[(kk + 1) * 64 + b_n] = v.y;
                Bd[(kk + 2) * 64 + b_n] = v.z;
                Bd[(kk + 3) * 64 + b_n] = v.w;
            }
        }

#pragma unroll 1
        for (int c = 0; c < 8; c++) {
            __syncthreads();
            if (c < 7) {
                const int kb = kg + (c + 1) * RN_KC;
                const int buf = (c + 1) & 1;
                const float4* ap = reinterpret_cast<const float4*>(
                    hsrc + (size_t)(m0 + a_row) * HH + kb + a_kofs);
                float* Ad = Asg + buf * RN_ABUF;
#pragma unroll
                for (int l = 0; l < 4; l++) {
                    float4 v = __ldcg(ap + l);
                    int kk = a_kofs + l * 4;
                    Ad[(kk + 0) * RN_LDA + a_row] = v.x;
                    Ad[(kk + 1) * RN_LDA + a_row] = v.y;
                    Ad[(kk + 2) * RN_LDA + a_row] = v.z;
                    Ad[(kk + 3) * RN_LDA + a_row] = v.w;
                }
                const float4* bp = reinterpret_cast<const float4*>(
                    Wh + (size_t)(n0 + b_n) * WSTRIDE + kb);
                float* Bd = Bsg + buf * RN_BBUF;
#pragma unroll
                for (int l = 0; l < 8; l++) {
                    float4 v = bp[l];
                    int kk = l * 4;
                    Bd[(kk + 0) * 64 + b_n] = v.x;
                    Bd[(kk + 1) * 64 + b_n] = v.y;
                    Bd[(kk + 2) * 64 + b_n] = v.z;
                    Bd[(kk + 3) * 64 + b_n] = v.w;
                }
            }
            const float* Ab = Asg + (c & 1) * RN_ABUF;
            const float* Bb = Bsg + (c & 1) * RN_BBUF;
#pragma unroll 8
            for (int kk = 0; kk < RN_KC; kk++) {
                float4 a = *reinterpret_cast<const float4*>(&Ab[kk * RN_LDA + ty * 4]);
                ulonglong2 b01 = *reinterpret_cast<const ulonglong2*>(&Bb[kk * 64 + tx * 8]);
                ulonglong2 b23 = *reinterpret_cast<const ulonglong2*>(&Bb[kk * 64 + tx * 8 + 4]);
                float av[4] = {a.x, a.y, a.z, a.w};
#pragma unroll
                for (int i = 0; i < 4; i++) {
                    ull ad = dup2(av[i]);
                    fma2(acc[i][0], ad, b01.x);
                    fma2(acc[i][1], ad, b01.y);
                    fma2(acc[i][2], ad, b23.x);
                    fma2(acc[i][3], ad, b23.y);
                }
            }
        }

        // ---- cross-group reduction through smem (reuses Bs region) --------
        __syncthreads();
#pragma unroll
        for (int i = 0; i < 4; i++)
#pragma unroll
            for (int j = 0; j < 4; j++)
                red[(size_t)g * 1024 + (ty * 4 + i) * 32 + tx * 4 + j] = acc[i][j];
        __syncthreads();

        {
            const float4* xp = reinterpret_cast<const float4*>(
                g_xproj + (size_t)t * BH + o_off);
            float4 r[2];
#pragma unroll
            for (int q = 0; q < 2; q++) {
                float4 x = __ldcs(xp + q);
                ull s0 = add2(add2(red[p0 + q * 2 + 0], red[1024 + p0 + q * 2 + 0]),
                              add2(red[2048 + p0 + q * 2 + 0], red[3072 + p0 + q * 2 + 0]));
                ull s1 = add2(add2(red[p0 + q * 2 + 1], red[1024 + p0 + q * 2 + 1]),
                              add2(red[2048 + p0 + q * 2 + 1], red[3072 + p0 + q * 2 + 1]));
                float2 e0 = unpack2(s0);
                float2 e1 = unpack2(s1);
                r[q] = make_float4(tanhf(e0.x + x.x), tanhf(e0.y + x.y),
                                   tanhf(e1.x + x.z), tanhf(e1.y + x.w));
            }
            if (t == TT - 1) {
                for (int cc = 0; cc < copies; cc++) {
                    float4* op = reinterpret_cast<float4*>(out + (size_t)cc * BH + o_off);
                    op[0] = r[0]; op[1] = r[1];
                }
            } else {
                float4* hd = reinterpret_cast<float4*>(g_h[t & 1] + o_off);
                hd[0] = r[0]; hd[1] = r[1];
            }
        }
    }

    // ---- exit: every CTA's final add strictly postdates its last in-loop
    // spin, so the reset below cannot strand an in-loop spinner. ------------
    __syncthreads();
    if (tid == 0) {
        __threadfence();
        atomicAdd(ctr, 1u);
        if (ni == 0) {
            while (*((volatile unsigned*)ctr) < (unsigned)TT * 16u) { __nanosleep(32); }
            atomicExch(ctr, 0u);
        }
    }
}

// ---------------------------------------------------------------------------
extern "C" void kernel_launch(void* const* d_in, const int* in_sizes, int n_in,
                              void* d_out, int out_size) {
    const float* xs = nullptr; const float* W = nullptr; const float* b = nullptr;
    for (int i = 0; i < n_in; i++) {
        if (in_sizes[i] == MTOT * DD)            xs = (const float*)d_in[i];
        else if (in_sizes[i] == HH * WSTRIDE)    W  = (const float*)d_in[i];
        else if (in_sizes[i] == HH)              b  = (const float*)d_in[i];
    }
    float* out = (float*)d_out;
    int copies = out_size / BH;
    if (copies < 1) copies = 1;
    if (copies > 2) copies = 2;

    static bool configured = false;
    if (!configured) {
        cudaFuncSetAttribute(recur_persistent,
                             cudaFuncAttributeMaxDynamicSharedMemorySize, RN_SMEM);
        configured = true;
    }

    xproj_gemm<<<dim3(HH / XP_BN, MTOT / XP_BM), 128>>>(xs, W, b);
    recur_persistent<<<dim3(16, 8), 256, RN_SMEM>>>(W, out, copies);
}

// round 10
// speedup vs baseline: 1.8194x; 1.7996x over previous
#include <cuda_runtime.h>
#include <cuda_bf16.h>
#include <math.h>
#include <stdint.h>

// Problem constants
#define BB   256
#define TT   512
#define DD   1024
#define HH   1024
#define MTOT (BB * TT)
#define BH   (BB * HH)
#define WSTRIDE (DD + HH)

// ---------------------------------------------------------------------------
// Scratch (device globals: allocation-free rule)
// ---------------------------------------------------------------------------
__device__ float g_xproj[134217728];             // [T][B][H]  512 MB
__device__ unsigned g_bar;                       // barrier counter
__device__ unsigned short g_hh[2][BH];           // h hi bf16, parity buffered
__device__ unsigned short g_hl[2][BH];           // h lo bf16
__device__ unsigned short g_whh[1024 * 1024];    // Wh hi bf16 [n][k]
__device__ unsigned short g_whl[1024 * 1024];    // Wh lo bf16 [n][k]

typedef unsigned long long ull;

// ---- packed fp32x2 helpers (xproj kernel) ---------------------------------
__device__ __forceinline__ void fma2(ull &d, ull a, ull b) {
    asm("fma.rn.f32x2 %0, %1, %2, %0;" : "+l"(d) : "l"(a), "l"(b));
}
__device__ __forceinline__ ull dup2(float a) {
    ull r; asm("mov.b64 %0, {%1, %1};" : "=l"(r) : "f"(a)); return r;
}
__device__ __forceinline__ float2 unpack2(ull v) {
    float2 r; asm("mov.b64 {%0, %1}, %2;" : "=f"(r.x), "=f"(r.y) : "l"(v)); return r;
}

// ---- mma.sync / ldmatrix helpers (baseline sm_80+ ISA, works on sm_100) ---
__device__ __forceinline__ uint32_t smem_u32(const void* p) {
    uint32_t a;
    asm("{ .reg .u64 t; cvta.to.shared.u64 t, %1; cvt.u32.u64 %0, t; }" : "=r"(a) : "l"(p));
    return a;
}
__device__ __forceinline__ void ldsm4(uint32_t& r0, uint32_t& r1, uint32_t& r2,
                                      uint32_t& r3, uint32_t addr) {
    asm volatile("ldmatrix.sync.aligned.m8n8.x4.shared.b16 {%0,%1,%2,%3}, [%4];"
                 : "=r"(r0), "=r"(r1), "=r"(r2), "=r"(r3) : "r"(addr));
}
__device__ __forceinline__ void mma16816(float* c, uint32_t a0, uint32_t a1,
                                         uint32_t a2, uint32_t a3,
                                         uint32_t b0, uint32_t b1) {
    asm volatile("mma.sync.aligned.m16n8k16.row.col.f32.bf16.bf16.f32 "
                 "{%0,%1,%2,%3}, {%4,%5,%6,%7}, {%8,%9}, {%0,%1,%2,%3};"
                 : "+f"(c[0]), "+f"(c[1]), "+f"(c[2]), "+f"(c[3])
                 : "r"(a0), "r"(a1), "r"(a2), "r"(a3), "r"(b0), "r"(b1));
}
__device__ __forceinline__ unsigned short bfbits(__nv_bfloat16 h) {
    return *reinterpret_cast<unsigned short*>(&h);
}

// ---------------------------------------------------------------------------
// Kernel 1: x_proj GEMM (unchanged, proven)
// ---------------------------------------------------------------------------
#define XP_BM 128
#define XP_BN 64
#define XP_BK 16
#define XP_LDA 132
#define XP_LDB 68

__global__ void __launch_bounds__(128) xproj_gemm(const float* __restrict__ xs,
                                                  const float* __restrict__ W,
                                                  const float* __restrict__ bias) {
    __shared__ __align__(16) float As[XP_BK][XP_LDA];
    __shared__ __align__(16) float Bs[XP_BK][XP_LDB];

    const int tid = threadIdx.x;
    const int tx = tid & 7;
    const int ty = tid >> 3;
    const int m0 = blockIdx.y * XP_BM;
    const int n0 = blockIdx.x * XP_BN;

    ull acc[8][4];
#pragma unroll
    for (int i = 0; i < 8; i++)
#pragma unroll
        for (int j = 0; j < 4; j++) acc[i][j] = 0ull;

    const float* Aptr = xs + (size_t)m0 * DD;
    const float* Bptr = W + (size_t)n0 * WSTRIDE;

    for (int kt = 0; kt < DD; kt += XP_BK) {
#pragma unroll
        for (int l = 0; l < 4; l++) {
            int j = tid + l * 128;
            int row = j >> 2, c4 = (j & 3) * 4;
            float4 v = *reinterpret_cast<const float4*>(Aptr + (size_t)row * DD + kt + c4);
            As[c4 + 0][row] = v.x; As[c4 + 1][row] = v.y;
            As[c4 + 2][row] = v.z; As[c4 + 3][row] = v.w;
        }
#pragma unroll
        for (int l = 0; l < 2; l++) {
            int j = tid + l * 128;
            int row = j >> 2, c4 = (j & 3) * 4;
            float4 v = *reinterpret_cast<const float4*>(Bptr + (size_t)row * WSTRIDE + kt + c4);
            Bs[c4 + 0][row] = v.x; Bs[c4 + 1][row] = v.y;
            Bs[c4 + 2][row] = v.z; Bs[c4 + 3][row] = v.w;
        }
        __syncthreads();
#pragma unroll
        for (int k = 0; k < XP_BK; k++) {
            float4 a0 = *reinterpret_cast<const float4*>(&As[k][ty * 8]);
            float4 a1 = *reinterpret_cast<const float4*>(&As[k][ty * 8 + 4]);
            ulonglong2 b0 = *reinterpret_cast<const ulonglong2*>(&Bs[k][tx * 8]);
            ulonglong2 b1 = *reinterpret_cast<const ulonglong2*>(&Bs[k][tx * 8 + 4]);
            float av[8] = {a0.x, a0.y, a0.z, a0.w, a1.x, a1.y, a1.z, a1.w};
            ull   bv[4] = {b0.x, b0.y, b1.x, b1.y};
#pragma unroll
            for (int i = 0; i < 8; i++) {
                ull ad = dup2(av[i]);
                fma2(acc[i][0], ad, bv[0]);
                fma2(acc[i][1], ad, bv[1]);
                fma2(acc[i][2], ad, bv[2]);
                fma2(acc[i][3], ad, bv[3]);
            }
        }
        __syncthreads();
    }

    const int nb = n0 + tx * 8;
    float4 bias0 = *reinterpret_cast<const float4*>(bias + nb);
    float4 bias1 = *reinterpret_cast<const float4*>(bias + nb + 4);
#pragma unroll
    for (int i = 0; i < 8; i++) {
        int mg = m0 + ty * 8 + i;
        int b_idx = mg >> 9;
        int t     = mg & 511;
        float* outp = g_xproj + ((size_t)t * BB + b_idx) * HH + nb;
        float2 v0 = unpack2(acc[i][0]);
        float2 v1 = unpack2(acc[i][1]);
        float2 v2 = unpack2(acc[i][2]);
        float2 v3 = unpack2(acc[i][3]);
        float4 o0 = make_float4(v0.x + bias0.x, v0.y + bias0.y, v1.x + bias0.z, v1.y + bias0.w);
        float4 o1 = make_float4(v2.x + bias1.x, v2.y + bias1.y, v3.x + bias1.z, v3.y + bias1.w);
        *reinterpret_cast<float4*>(outp)     = o0;
        *reinterpret_cast<float4*>(outp + 4) = o1;
    }
}

// ---------------------------------------------------------------------------
// Kernel 2: Wh -> bf16 hi/lo split, plain [n][k] row-major.
// ---------------------------------------------------------------------------
__global__ void __launch_bounds__(256) wh_prep(const float* __restrict__ W) {
    int idx = blockIdx.x * 256 + threadIdx.x;       // 0 .. 2^20-1
    int n = idx >> 10, k = idx & 1023;
    float w = W[(size_t)n * WSTRIDE + DD + k];
    __nv_bfloat16 hi = __float2bfloat16(w);
    __nv_bfloat16 lo = __float2bfloat16(w - __bfloat162float(hi));
    g_whh[idx] = bfbits(hi);
    g_whl[idx] = bfbits(lo);
}

// ---------------------------------------------------------------------------
// Kernel 3: persistent HMMA recurrence.
// Grid (32, 4) = 128 CTAs (1/SM), 256 threads = 8 warps (4m x 2n).
// CTA tile 64(M) x 32(N), K = 1024. Wh slice (32n x 1024k, hi/lo bf16,
// stride 1032) RESIDENT in smem for all steps. h is kept in global as
// bf16 hi/lo (parity double-buffered); per step A chunks of k=64 are
// staged (LDG.128 -> STS.128) double-buffered. Warp tile 16m x 16n:
// per k16: 2 A-ldmatrix.x4 (hi,lo) + 2 B-ldmatrix.x4 (hi,lo) + 6 mma
// (hh, hl, lh). Epilogue: acc + xp -> tanh -> split -> store bf16 h.
// ---------------------------------------------------------------------------
#define RB_STRIDE 1032                      // B smem row stride (elems)
#define RB_SIZE   (32 * RB_STRIDE * 2)      // 66048 B per B array
#define RA_STRIDE 72                        // A smem row stride (elems)
#define RA_SIZE   (64 * RA_STRIDE * 2)      // 9216 B per A array
#define A_OFF     (2 * RB_SIZE)             // 132096
#define A_BUFSZ   (2 * RA_SIZE)             // hi+lo = 18432
#define RC_SMEM   (A_OFF + 2 * A_BUFSZ)     // 168960 B

__device__ __forceinline__ void stage_A(char* smem, int par, int m0, int kc, int bb,
                                        int tid) {
    const unsigned short* sh = g_hh[par];
    const unsigned short* sl = g_hl[par];
#pragma unroll
    for (int q = 0; q < 2; q++) {
        int i = tid + q * 256;
        int row = i >> 3, ko = (i & 7) * 8;
        size_t src = (size_t)(m0 + row) * HH + kc + ko;
        uint4 vh = *reinterpret_cast<const uint4*>(sh + src);
        *reinterpret_cast<uint4*>(smem + A_OFF + bb * A_BUFSZ +
                                  (row * RA_STRIDE + ko) * 2) = vh;
        uint4 vl = *reinterpret_cast<const uint4*>(sl + src);
        *reinterpret_cast<uint4*>(smem + A_OFF + bb * A_BUFSZ + RA_SIZE +
                                  (row * RA_STRIDE + ko) * 2) = vl;
    }
}

__global__ void __launch_bounds__(256, 1)
recur_hmma(float* __restrict__ out, int copies) {
    extern __shared__ __align__(16) char smem[];
    const uint32_t sb = smem_u32(smem);
    const int tid  = threadIdx.x;
    const int wid  = tid >> 5;
    const int lane = tid & 31;
    const int ni = blockIdx.x;              // 0..31
    const int mi = blockIdx.y;              // 0..3
    const int m0 = mi * 64;
    const int n0 = ni * 32;
    const int wm = wid >> 1;                // 0..3 -> m offset 16
    const int wn = wid & 1;                 // 0..1 -> n offset 16
    const int gid = lane >> 2, tig = lane & 3;

    // ---- stage resident Wh slice (rows [n0,+32), hi/lo) -------------------
#pragma unroll
    for (int q = 0; q < 16; q++) {
        int i = tid + q * 256;
        int row = i >> 7, ko = (i & 127) * 8;
        size_t src = (size_t)(n0 + row) * 1024 + ko;
        uint4 vh = *reinterpret_cast<const uint4*>(g_whh + src);
        *reinterpret_cast<uint4*>(smem + (row * RB_STRIDE + ko) * 2) = vh;
        uint4 vl = *reinterpret_cast<const uint4*>(g_whl + src);
        *reinterpret_cast<uint4*>(smem + RB_SIZE + (row * RB_STRIDE + ko) * 2) = vl;
    }

    // ---- Step 0: h0 = 0 -> h[0] = split(tanh(x_proj[0])) on own tile ------
#pragma unroll
    for (int q = 0; q < 2; q++) {
        int i = tid + q * 256;
        int row = i >> 3, c4 = (i & 7) * 4;
        size_t off = (size_t)(m0 + row) * HH + n0 + c4;
        float4 v = __ldcs(reinterpret_cast<const float4*>(g_xproj + off));
        float o[4] = {tanhf(v.x), tanhf(v.y), tanhf(v.z), tanhf(v.w)};
        unsigned hh[2], hl[2];
#pragma unroll
        for (int p = 0; p < 2; p++) {
            __nv_bfloat16 h0 = __float2bfloat16(o[2 * p]);
            __nv_bfloat16 h1 = __float2bfloat16(o[2 * p + 1]);
            __nv_bfloat16 l0 = __float2bfloat16(o[2 * p] - __bfloat162float(h0));
            __nv_bfloat16 l1 = __float2bfloat16(o[2 * p + 1] - __bfloat162float(h1));
            hh[p] = (unsigned)bfbits(h0) | ((unsigned)bfbits(h1) << 16);
            hl[p] = (unsigned)bfbits(l0) | ((unsigned)bfbits(l1) << 16);
        }
        *reinterpret_cast<uint2*>(&g_hh[0][off]) = make_uint2(hh[0], hh[1]);
        *reinterpret_cast<uint2*>(&g_hl[0][off]) = make_uint2(hl[0], hl[1]);
    }

    // ---- per-lane ldmatrix addresses --------------------------------------
    // A frag (16m x 16k): reg order (m0,k0),(m8,k0),(m0,k8),(m8,k8)
    const int a_row = (lane & 7) + ((lane >> 3) & 1) * 8 + wm * 16;
    const int a_kad = (lane >> 4) * 8;
    const uint32_t a_off = (uint32_t)((a_row * RA_STRIDE + a_kad) * 2);
    // B frag pair (16n x 16k): reg order (n0,k0),(n0,k8),(n8,k0),(n8,k8)
    const int b_row = (lane & 7) + (lane >> 4) * 8 + wn * 16;
    const int b_kad = ((lane >> 3) & 1) * 8;
    const uint32_t b_off = (uint32_t)((b_row * RB_STRIDE + b_kad) * 2);

    for (int t = 1; t < TT; t++) {
        // global barrier over 128 CTAs (monotone counter, bounded spin)
        __syncthreads();
        if (tid == 0) {
            __threadfence();
            atomicAdd(&g_bar, 1u);
            unsigned tgt = (unsigned)t * 128u;
            for (int it = 0; it < (1 << 18); ++it) {
                if (*((volatile unsigned*)&g_bar) >= tgt) break;
                __nanosleep(64);
            }
            __threadfence();
        }
        __syncthreads();

        const int par = (t - 1) & 1;
        float acc[2][4];
#pragma unroll
        for (int i = 0; i < 2; i++)
#pragma unroll
            for (int j = 0; j < 4; j++) acc[i][j] = 0.0f;

        stage_A(smem, par, m0, 0, 0, tid);

#pragma unroll 1
        for (int c = 0; c < 16; c++) {
            __syncthreads();
            if (c < 15) stage_A(smem, par, m0, (c + 1) * 64, (c + 1) & 1, tid);

            const uint32_t ab = sb + A_OFF + (c & 1) * A_BUFSZ;
            const uint32_t bkofs = (uint32_t)(c * 64 * 2);
#pragma unroll
            for (int ks = 0; ks < 4; ks++) {
                uint32_t ah0, ah1, ah2, ah3, al0, al1, al2, al3;
                uint32_t bh0, bh1, bh2, bh3, bl0, bl1, bl2, bl3;
                ldsm4(ah0, ah1, ah2, ah3, ab + a_off + ks * 32);
                ldsm4(al0, al1, al2, al3, ab + RA_SIZE + a_off + ks * 32);
                ldsm4(bh0, bh1, bh2, bh3, sb + b_off + bkofs + ks * 32);
                ldsm4(bl0, bl1, bl2, bl3, sb + RB_SIZE + b_off + bkofs + ks * 32);
                mma16816(acc[0], ah0, ah1, ah2, ah3, bh0, bh1);
                mma16816(acc[1], ah0, ah1, ah2, ah3, bh2, bh3);
                mma16816(acc[0], ah0, ah1, ah2, ah3, bl0, bl1);
                mma16816(acc[1], ah0, ah1, ah2, ah3, bl2, bl3);
                mma16816(acc[0], al0, al1, al2, al3, bh0, bh1);
                mma16816(acc[1], al0, al1, al2, al3, bh2, bh3);
            }
        }

        // ---- epilogue: acc + xp -> tanh -> split -> h (or out) ------------
        {
            const float* xpt = g_xproj + (size_t)t * BH;
            const int wpar = t & 1;
#pragma unroll
            for (int half = 0; half < 2; half++) {
                const int r = m0 + wm * 16 + gid + half * 8;
#pragma unroll
                for (int nt = 0; nt < 2; nt++) {
                    const int cn = n0 + wn * 16 + nt * 8 + tig * 2;
                    const size_t off = (size_t)r * HH + cn;
                    float2 x = *reinterpret_cast<const float2*>(xpt + off);
                    float o0 = tanhf(acc[nt][half * 2 + 0] + x.x);
                    float o1 = tanhf(acc[nt][half * 2 + 1] + x.y);
                    if (t == TT - 1) {
                        for (int cc = 0; cc < copies; cc++)
                            *reinterpret_cast<float2*>(out + (size_t)cc * BH + off) =
                                make_float2(o0, o1);
                    } else {
                        __nv_bfloat16 h0 = __float2bfloat16(o0);
                        __nv_bfloat16 h1 = __float2bfloat16(o1);
                        __nv_bfloat16 l0 = __float2bfloat16(o0 - __bfloat162float(h0));
                        __nv_bfloat16 l1 = __float2bfloat16(o1 - __bfloat162float(h1));
                        *reinterpret_cast<unsigned*>(&g_hh[wpar][off]) =
                            (unsigned)bfbits(h0) | ((unsigned)bfbits(h1) << 16);
                        *reinterpret_cast<unsigned*>(&g_hl[wpar][off]) =
                            (unsigned)bfbits(l0) | ((unsigned)bfbits(l1) << 16);
                    }
                }
            }
        }
    }

    // ---- exit barrier + protected, bounded counter reset ------------------
    __syncthreads();
    if (tid == 0) {
        __threadfence();
        atomicAdd(&g_bar, 1u);
        if (ni == 0 && mi == 0) {
            for (int it = 0; it < (1 << 20); ++it) {
                if (*((volatile unsigned*)&g_bar) >= (unsigned)TT * 128u) break;
                __nanosleep(64);
            }
            atomicExch(&g_bar, 0u);
        }
    }
}

// ---------------------------------------------------------------------------
extern "C" void kernel_launch(void* const* d_in, const int* in_sizes, int n_in,
                              void* d_out, int out_size) {
    const float* xs = nullptr; const float* W = nullptr; const float* b = nullptr;
    for (int i = 0; i < n_in; i++) {
        if (in_sizes[i] == MTOT * DD)            xs = (const float*)d_in[i];
        else if (in_sizes[i] == HH * WSTRIDE)    W  = (const float*)d_in[i];
        else if (in_sizes[i] == HH)              b  = (const float*)d_in[i];
    }
    float* out = (float*)d_out;
    int copies = out_size / BH;
    if (copies < 1) copies = 1;
    if (copies > 2) copies = 2;

    static bool configured = false;
    if (!configured) {
        cudaFuncSetAttribute(recur_hmma,
                             cudaFuncAttributeMaxDynamicSharedMemorySize, RC_SMEM);
        configured = true;
    }

    xproj_gemm<<<dim3(HH / XP_BN, MTOT / XP_BM), 128>>>(xs, W, b);
    wh_prep<<<4096, 256>>>(W);
    recur_hmma<<<dim3(32, 4), 256, RC_SMEM>>>(out, copies);
}

// round 12
// speedup vs baseline: 2.9520x; 1.6225x over previous
#include <cuda_runtime.h>
#include <cuda_bf16.h>
#include <math.h>
#include <stdint.h>

// Problem constants
#define BB   256
#define TT   512
#define DD   1024
#define HH   1024
#define MTOT (BB * TT)
#define BH   (BB * HH)
#define WSTRIDE (DD + HH)

// ---------------------------------------------------------------------------
// Scratch (device globals: allocation-free rule)
// ---------------------------------------------------------------------------
__device__ float g_xproj[134217728];             // [T][B][H]  512 MB
__device__ unsigned g_barM[4 * 32];              // 4 band barrier counters
__device__ unsigned short g_hh[2][BH];           // h hi bf16, parity buffered
__device__ unsigned short g_hl[2][BH];           // h lo bf16
__device__ unsigned short g_whh[1024 * 1024];    // Wh hi bf16 [n][k]
__device__ unsigned short g_whl[1024 * 1024];    // Wh lo bf16 [n][k]
__device__ unsigned short g_wxh[1024 * 1024];    // Wx hi bf16 [n][k]
__device__ unsigned short g_wxl[1024 * 1024];    // Wx lo bf16 [n][k]
__device__ unsigned short g_xh[134217728];       // xs hi bf16 [MTOT][D] 256 MB
__device__ unsigned short g_xl[134217728];       // xs lo bf16 [MTOT][D] 256 MB

// ---- mma.sync / ldmatrix / cp.async helpers (baseline sm_80+ ISA) ---------
__device__ __forceinline__ uint32_t smem_u32(const void* p) {
    uint32_t a;
    asm("{ .reg .u64 t; cvta.to.shared.u64 t, %1; cvt.u32.u64 %0, t; }" : "=r"(a) : "l"(p));
    return a;
}
__device__ __forceinline__ void ldsm4(uint32_t& r0, uint32_t& r1, uint32_t& r2,
                                      uint32_t& r3, uint32_t addr) {
    asm volatile("ldmatrix.sync.aligned.m8n8.x4.shared.b16 {%0,%1,%2,%3}, [%4];"
                 : "=r"(r0), "=r"(r1), "=r"(r2), "=r"(r3) : "r"(addr));
}
__device__ __forceinline__ void mma16816(float* c, uint32_t a0, uint32_t a1,
                                         uint32_t a2, uint32_t a3,
                                         uint32_t b0, uint32_t b1) {
    asm volatile("mma.sync.aligned.m16n8k16.row.col.f32.bf16.bf16.f32 "
                 "{%0,%1,%2,%3}, {%4,%5,%6,%7}, {%8,%9}, {%0,%1,%2,%3};"
                 : "+f"(c[0]), "+f"(c[1]), "+f"(c[2]), "+f"(c[3])
                 : "r"(a0), "r"(a1), "r"(a2), "r"(a3), "r"(b0), "r"(b1));
}
__device__ __forceinline__ void cpa16(uint32_t dst, const void* src) {
    size_t g = __cvta_generic_to_global(src);
    asm volatile("cp.async.cg.shared.global [%0], [%1], 16;" :: "r"(dst), "l"(g) : "memory");
}
#define CPA_COMMIT() asm volatile("cp.async.commit_group;" ::: "memory")
#define CPA_WAIT(n)  asm volatile("cp.async.wait_group %0;" :: "n"(n) : "memory")

__device__ __forceinline__ unsigned short bfbits(__nv_bfloat16 h) {
    return *reinterpret_cast<unsigned short*>(&h);
}
__device__ __forceinline__ unsigned pack_hi(float a, float b) {
    __nv_bfloat16 h0 = __float2bfloat16(a), h1 = __float2bfloat16(b);
    return (unsigned)bfbits(h0) | ((unsigned)bfbits(h1) << 16);
}
__device__ __forceinline__ unsigned pack_lo(float a, float b) {
    __nv_bfloat16 h0 = __float2bfloat16(a), h1 = __float2bfloat16(b);
    __nv_bfloat16 l0 = __float2bfloat16(a - __bfloat162float(h0));
    __nv_bfloat16 l1 = __float2bfloat16(b - __bfloat162float(h1));
    return (unsigned)bfbits(l0) | ((unsigned)bfbits(l1) << 16);
}

// ---------------------------------------------------------------------------
// Prep kernels: split xs / Wx / Wh into bf16 hi+lo
// ---------------------------------------------------------------------------
__global__ void __launch_bounds__(256) xsplit(const float* __restrict__ xs) {
    size_t i4 = ((size_t)blockIdx.x * 256 + threadIdx.x) * 4;
    float4 v = *reinterpret_cast<const float4*>(xs + i4);
    *reinterpret_cast<uint2*>(g_xh + i4) =
        make_uint2(pack_hi(v.x, v.y), pack_hi(v.z, v.w));
    *reinterpret_cast<uint2*>(g_xl + i4) =
        make_uint2(pack_lo(v.x, v.y), pack_lo(v.z, v.w));
}
__global__ void __launch_bounds__(256) w_prep(const float* __restrict__ W) {
    int idx = blockIdx.x * 256 + threadIdx.x;       // 0 .. 2^20-1
    int n = idx >> 10, k = idx & 1023;
    float wx = W[(size_t)n * WSTRIDE + k];
    __nv_bfloat16 xh = __float2bfloat16(wx);
    g_wxh[idx] = bfbits(xh);
    g_wxl[idx] = bfbits(__float2bfloat16(wx - __bfloat162float(xh)));
    float wh = W[(size_t)n * WSTRIDE + DD + k];
    __nv_bfloat16 hh = __float2bfloat16(wh);
    g_whh[idx] = bfbits(hh);
    g_whl[idx] = bfbits(__float2bfloat16(wh - __bfloat162float(hh)));
}

// ---------------------------------------------------------------------------
// Kernel 1: x_proj HMMA GEMM. Grid (16 n-tiles, 1024 m-tiles), 256 threads.
// CTA tile 128m x 64n, K=1024 in 16 chunks of 64, cp.async 3-buffer pipeline.
// 8 warps = 4m x 2n; warp tile 32m x 32n; hi/lo split (hh+hl+lh), fp32 acc.
// Epilogue adds bias and writes fp32 to g_xproj with (b,t)->(t,b) remap.
// ---------------------------------------------------------------------------
#define XS 72                                  // smem row stride (elems)
#define X_RA_SIZE (128 * XS * 2)               // 18432 B (one array)
#define X_ABUF (2 * X_RA_SIZE)                 // hi+lo = 36864
#define X_RB_SIZE (64 * XS * 2)                // 9216 B
#define X_BBUF (2 * X_RB_SIZE)                 // 18432
#define XP2_SMEM (3 * (X_ABUF + X_BBUF))       // 165888 B

__device__ __forceinline__ void xstage(uint32_t sb, int buf, int gm0, int n0,
                                       int kc, int tid) {
#pragma unroll
    for (int q = 0; q < 4; q++) {
        int i = tid + q * 256;
        int row = i >> 3, ko = (i & 7) * 8;
        size_t src = (size_t)(gm0 + row) * 1024 + kc + ko;
        uint32_t dst = sb + buf * X_ABUF + (uint32_t)((row * XS + ko) * 2);
        cpa16(dst, g_xh + src);
        cpa16(dst + X_RA_SIZE, g_xl + src);
    }
#pragma unroll
    for (int q = 0; q < 2; q++) {
        int i = tid + q * 256;
        int row = i >> 3, ko = (i & 7) * 8;
        size_t src = (size_t)(n0 + row) * 1024 + kc + ko;
        uint32_t dst = sb + 3 * X_ABUF + buf * X_BBUF + (uint32_t)((row * XS + ko) * 2);
        cpa16(dst, g_wxh + src);
        cpa16(dst + X_RB_SIZE, g_wxl + src);
    }
}

__global__ void __launch_bounds__(256, 1)
xproj_hmma(const float* __restrict__ bias) {
    extern __shared__ __align__(16) char smem[];
    const uint32_t sb = smem_u32(smem);
    const int tid  = threadIdx.x;
    const int wid  = tid >> 5;
    const int lane = tid & 31;
    const int n0  = blockIdx.x * 64;
    const int gm0 = blockIdx.y * 128;
    const int wm = wid >> 1, wn = wid & 1;
    const int gid = lane >> 2, tig = lane & 3;

    uint32_t a_off[2], b_off[2];
#pragma unroll
    for (int mt = 0; mt < 2; mt++)
        a_off[mt] = (uint32_t)(((wm * 32 + mt * 16 + (lane & 7) + ((lane >> 3) & 1) * 8) * XS
                                + (lane >> 4) * 8) * 2);
#pragma unroll
    for (int nt = 0; nt < 2; nt++)
        b_off[nt] = (uint32_t)(((wn * 32 + nt * 16 + (lane & 7) + (lane >> 4) * 8) * XS
                                + ((lane >> 3) & 1) * 8) * 2);

    float acc[2][4][4];
#pragma unroll
    for (int i = 0; i < 2; i++)
#pragma unroll
        for (int j = 0; j < 4; j++)
#pragma unroll
            for (int q = 0; q < 4; q++) acc[i][j][q] = 0.0f;

    xstage(sb, 0, gm0, n0, 0, tid);  CPA_COMMIT();
    xstage(sb, 1, gm0, n0, 64, tid); CPA_COMMIT();

#pragma unroll 1
    for (int c = 0; c < 16; c++) {
        CPA_WAIT(1);
        __syncthreads();
        if (c + 2 < 16) xstage(sb, (c + 2) % 3, gm0, n0, (c + 2) * 64, tid);
        CPA_COMMIT();

        const uint32_t ab = sb + (c % 3) * X_ABUF;
        const uint32_t bb = sb + 3 * X_ABUF + (c % 3) * X_BBUF;
#pragma unroll
        for (int ks = 0; ks < 4; ks++) {
            uint32_t AH[2][4], AL[2][4];
#pragma unroll
            for (int mt = 0; mt < 2; mt++) {
                ldsm4(AH[mt][0], AH[mt][1], AH[mt][2], AH[mt][3], ab + a_off[mt] + ks * 32);
                ldsm4(AL[mt][0], AL[mt][1], AL[mt][2], AL[mt][3],
                      ab + X_RA_SIZE + a_off[mt] + ks * 32);
            }
#pragma unroll
            for (int nt = 0; nt < 2; nt++) {
                uint32_t bh0, bh1, bh2, bh3, bl0, bl1, bl2, bl3;
                ldsm4(bh0, bh1, bh2, bh3, bb + b_off[nt] + ks * 32);
                ldsm4(bl0, bl1, bl2, bl3, bb + X_RB_SIZE + b_off[nt] + ks * 32);
#pragma unroll
                for (int mt = 0; mt < 2; mt++) {
                    mma16816(acc[mt][nt * 2 + 0], AH[mt][0], AH[mt][1], AH[mt][2], AH[mt][3], bh0, bh1);
                    mma16816(acc[mt][nt * 2 + 1], AH[mt][0], AH[mt][1], AH[mt][2], AH[mt][3], bh2, bh3);
                    mma16816(acc[mt][nt * 2 + 0], AH[mt][0], AH[mt][1], AH[mt][2], AH[mt][3], bl0, bl1);
                    mma16816(acc[mt][nt * 2 + 1], AH[mt][0], AH[mt][1], AH[mt][2], AH[mt][3], bl2, bl3);
                    mma16816(acc[mt][nt * 2 + 0], AL[mt][0], AL[mt][1], AL[mt][2], AL[mt][3], bh0, bh1);
                    mma16816(acc[mt][nt * 2 + 1], AL[mt][0], AL[mt][1], AL[mt][2], AL[mt][3], bh2, bh3);
                }
            }
        }
    }

    // epilogue: + bias, remap row (b*T + t) -> x_proj[t][b][:]
    float2 bias2[4];
#pragma unroll
    for (int nq = 0; nq < 4; nq++) {
        int cn = n0 + wn * 32 + (nq >> 1) * 16 + (nq & 1) * 8 + tig * 2;
        bias2[nq] = *reinterpret_cast<const float2*>(bias + cn);
    }
#pragma unroll
    for (int mt = 0; mt < 2; mt++) {
#pragma unroll
        for (int half = 0; half < 2; half++) {
            int gm = gm0 + wm * 32 + mt * 16 + gid + half * 8;
            int b_idx = gm >> 9, tq = gm & 511;
            float* orow = g_xproj + ((size_t)tq * BB + b_idx) * HH;
#pragma unroll
            for (int nq = 0; nq < 4; nq++) {
                int cn = n0 + wn * 32 + (nq >> 1) * 16 + (nq & 1) * 8 + tig * 2;
                *reinterpret_cast<float2*>(orow + cn) =
                    make_float2(acc[mt][nq][half * 2 + 0] + bias2[nq].x,
                                acc[mt][nq][half * 2 + 1] + bias2[nq].y);
            }
        }
    }
}

// ---------------------------------------------------------------------------
// Kernel 2: persistent HMMA recurrence (cp.async 4-buffer A pipeline,
// band barriers). Grid (32 ni, 4 mi) = 128 CTAs, 256 threads = 8 warps.
// CTA tile 64m x 32n; Wh slice resident in smem; h in global bf16 hi/lo.
// ---------------------------------------------------------------------------
#define RB_STRIDE 1032
#define RB_SIZE   (32 * RB_STRIDE * 2)      // 66048 B
#define RA_STRIDE 72
#define RA_SIZE   (64 * RA_STRIDE * 2)      // 9216 B
#define A_OFF     (2 * RB_SIZE)             // 132096
#define A_BUFSZ   (2 * RA_SIZE)             // 18432
#define RC_SMEM   (A_OFF + 4 * A_BUFSZ)     // 205824 B

__device__ __forceinline__ void stage_A(uint32_t sb, int par, int m0, int kc,
                                        int buf, int tid) {
    const unsigned short* sh = g_hh[par];
    const unsigned short* sl = g_hl[par];
#pragma unroll
    for (int q = 0; q < 2; q++) {
        int i = tid + q * 256;
        int row = i >> 3, ko = (i & 7) * 8;
        size_t src = (size_t)(m0 + row) * HH + kc + ko;
        uint32_t dst = sb + A_OFF + buf * A_BUFSZ + (uint32_t)((row * RA_STRIDE + ko) * 2);
        cpa16(dst, sh + src);
        cpa16(dst + RA_SIZE, sl + src);
    }
}

__global__ void __launch_bounds__(256, 1)
recur_hmma(float* __restrict__ out, int copies) {
    extern __shared__ __align__(16) char smem[];
    const uint32_t sb = smem_u32(smem);
    const int tid  = threadIdx.x;
    const int wid  = tid >> 5;
    const int lane = tid & 31;
    const int ni = blockIdx.x;              // 0..31
    const int mi = blockIdx.y;              // 0..3
    const int m0 = mi * 64;
    const int n0 = ni * 32;
    const int wm = wid >> 1, wn = wid & 1;
    const int gid = lane >> 2, tig = lane & 3;
    unsigned* ctr = &g_barM[mi * 32];

    // ---- stage resident Wh slice (rows [n0,+32), hi/lo) -------------------
#pragma unroll
    for (int q = 0; q < 16; q++) {
        int i = tid + q * 256;
        int row = i >> 7, ko = (i & 127) * 8;
        size_t src = (size_t)(n0 + row) * 1024 + ko;
        uint4 vh = *reinterpret_cast<const uint4*>(g_whh + src);
        *reinterpret_cast<uint4*>(smem + (row * RB_STRIDE + ko) * 2) = vh;
        uint4 vl = *reinterpret_cast<const uint4*>(g_whl + src);
        *reinterpret_cast<uint4*>(smem + RB_SIZE + (row * RB_STRIDE + ko) * 2) = vl;
    }

    // ---- Step 0: h0 = 0 -> h[0] = split(tanh(x_proj[0])) on own tile ------
#pragma unroll
    for (int q = 0; q < 2; q++) {
        int i = tid + q * 256;
        int row = i >> 3, c4 = (i & 7) * 4;
        size_t off = (size_t)(m0 + row) * HH + n0 + c4;
        float4 v = __ldcs(reinterpret_cast<const float4*>(g_xproj + off));
        float o[4] = {tanhf(v.x), tanhf(v.y), tanhf(v.z), tanhf(v.w)};
        *reinterpret_cast<uint2*>(&g_hh[0][off]) =
            make_uint2(pack_hi(o[0], o[1]), pack_hi(o[2], o[3]));
        *reinterpret_cast<uint2*>(&g_hl[0][off]) =
            make_uint2(pack_lo(o[0], o[1]), pack_lo(o[2], o[3]));
    }

    // per-lane ldmatrix addresses (warp tile 16m x 16n)
    const int a_row = (lane & 7) + ((lane >> 3) & 1) * 8 + wm * 16;
    const uint32_t a_off = (uint32_t)((a_row * RA_STRIDE + (lane >> 4) * 8) * 2);
    const int b_row = (lane & 7) + (lane >> 4) * 8 + wn * 16;
    const uint32_t b_off = (uint32_t)((b_row * RB_STRIDE + ((lane >> 3) & 1) * 8) * 2);

    for (int t = 1; t < TT; t++) {
        // band barrier over 32 CTAs (monotone counter, bounded spin)
        __syncthreads();
        if (tid == 0) {
            __threadfence();
            atomicAdd(ctr, 1u);
            unsigned tgt = (unsigned)t * 32u;
            for (int it = 0; it < (1 << 18); ++it) {
                if (*((volatile unsigned*)ctr) >= tgt) break;
                __nanosleep(64);
            }
            __threadfence();
        }
        __syncthreads();

        const int par = (t - 1) & 1;
        float acc[2][4];
#pragma unroll
        for (int i = 0; i < 2; i++)
#pragma unroll
            for (int j = 0; j < 4; j++) acc[i][j] = 0.0f;

        stage_A(sb, par, m0, 0,   0, tid); CPA_COMMIT();
        stage_A(sb, par, m0, 64,  1, tid); CPA_COMMIT();
        stage_A(sb, par, m0, 128, 2, tid); CPA_COMMIT();

#pragma unroll 1
        for (int c = 0; c < 16; c++) {
            CPA_WAIT(2);
            __syncthreads();
            if (c + 3 < 16) stage_A(sb, par, m0, (c + 3) * 64, (c + 3) & 3, tid);
            CPA_COMMIT();

            const uint32_t ab = sb + A_OFF + (c & 3) * A_BUFSZ;
            const uint32_t bkofs = (uint32_t)(c * 64 * 2);
#pragma unroll
            for (int ks = 0; ks < 4; ks++) {
                uint32_t ah0, ah1, ah2, ah3, al0, al1, al2, al3;
                uint32_t bh0, bh1, bh2, bh3, bl0, bl1, bl2, bl3;
                ldsm4(ah0, ah1, ah2, ah3, ab + a_off + ks * 32);
                ldsm4(al0, al1, al2, al3, ab + RA_SIZE + a_off + ks * 32);
                ldsm4(bh0, bh1, bh2, bh3, sb + b_off + bkofs + ks * 32);
                ldsm4(bl0, bl1, bl2, bl3, sb + RB_SIZE + b_off + bkofs + ks * 32);
                mma16816(acc[0], ah0, ah1, ah2, ah3, bh0, bh1);
                mma16816(acc[1], ah0, ah1, ah2, ah3, bh2, bh3);
                mma16816(acc[0], ah0, ah1, ah2, ah3, bl0, bl1);
                mma16816(acc[1], ah0, ah1, ah2, ah3, bl2, bl3);
                mma16816(acc[0], al0, al1, al2, al3, bh0, bh1);
                mma16816(acc[1], al0, al1, al2, al3, bh2, bh3);
            }
        }

        // ---- epilogue: acc + xp -> tanh -> split -> h (or out) ------------
        {
            const float* xpt = g_xproj + (size_t)t * BH;
            const int wpar = t & 1;
#pragma unroll
            for (int half = 0; half < 2; half++) {
                const int r = m0 + wm * 16 + gid + half * 8;
#pragma unroll
                for (int nt = 0; nt < 2; nt++) {
                    const int cn = n0 + wn * 16 + nt * 8 + tig * 2;
                    const size_t off = (size_t)r * HH + cn;
                    float2 x = *reinterpret_cast<const float2*>(xpt + off);
                    float o0 = tanhf(acc[nt][half * 2 + 0] + x.x);
                    float o1 = tanhf(acc[nt][half * 2 + 1] + x.y);
                    if (t == TT - 1) {
                        for (int cc = 0; cc < copies; cc++)
                            *reinterpret_cast<float2*>(out + (size_t)cc * BH + off) =
                                make_float2(o0, o1);
                    } else {
                        *reinterpret_cast<unsigned*>(&g_hh[wpar][off]) = pack_hi(o0, o1);
                        *reinterpret_cast<unsigned*>(&g_hl[wpar][off]) = pack_lo(o0, o1);
                    }
                }
            }
        }
    }

    // ---- exit: band-local barrier + protected, bounded counter reset ------
    __syncthreads();
    if (tid == 0) {
        __threadfence();
        atomicAdd(ctr, 1u);
        if (ni == 0) {
            for (int it = 0; it < (1 << 20); ++it) {
                if (*((volatile unsigned*)ctr) >= (unsigned)TT * 32u) break;
                __nanosleep(64);
            }
            atomicExch(ctr, 0u);
        }
    }
}

// ---------------------------------------------------------------------------
extern "C" void kernel_launch(void* const* d_in, const int* in_sizes, int n_in,
                              void* d_out, int out_size) {
    const float* xs = nullptr; const float* W = nullptr; const float* b = nullptr;
    for (int i = 0; i < n_in; i++) {
        if (in_sizes[i] == MTOT * DD)            xs = (const float*)d_in[i];
        else if (in_sizes[i] == HH * WSTRIDE)    W  = (const float*)d_in[i];
        else if (in_sizes[i] == HH)              b  = (const float*)d_in[i];
    }
    float* out = (float*)d_out;
    int copies = out_size / BH;
    if (copies < 1) copies = 1;
    if (copies > 2) copies = 2;

    static bool configured = false;
    if (!configured) {
        cudaFuncSetAttribute(xproj_hmma,
                             cudaFuncAttributeMaxDynamicSharedMemorySize, XP2_SMEM);
        cudaFuncSetAttribute(recur_hmma,
                             cudaFuncAttributeMaxDynamicSharedMemorySize, RC_SMEM);
        configured = true;
    }

    xsplit<<<131072, 256>>>(xs);
    w_prep<<<4096, 256>>>(W);
    xproj_hmma<<<dim3(16, 1024), 256, XP2_SMEM>>>(b);
    recur_hmma<<<dim3(32, 4), 256, RC_SMEM>>>(out, copies);
}

// round 13
// speedup vs baseline: 3.3968x; 1.1507x over previous
#include <cuda_runtime.h>
#include <cuda_bf16.h>
#include <math.h>
#include <stdint.h>

// Problem constants
#define BB   256
#define TT   512
#define DD   1024
#define HH   1024
#define MTOT (BB * TT)
#define BH   (BB * HH)
#define WSTRIDE (DD + HH)

// ---------------------------------------------------------------------------
// Scratch (device globals: allocation-free rule)
// ---------------------------------------------------------------------------
__device__ float g_xproj[134217728];             // [T][B][H]  512 MB
__device__ unsigned g_barM[4 * 32];              // 4 band barrier counters
__device__ unsigned short g_hh[2][BH];           // h hi bf16, parity buffered
__device__ unsigned short g_hl[2][BH];           // h lo bf16
__device__ unsigned short g_whh[1024 * 1024];    // Wh hi bf16 [n][k]
__device__ unsigned short g_whl[1024 * 1024];    // Wh lo bf16 [n][k]
__device__ unsigned short g_wxh[1024 * 1024];    // Wx hi bf16 [n][k]
__device__ unsigned short g_wxl[1024 * 1024];    // Wx lo bf16 [n][k]
__device__ unsigned short g_xh[134217728];       // xs hi bf16 [MTOT][D] 256 MB
__device__ unsigned short g_xl[134217728];       // xs lo bf16 [MTOT][D] 256 MB

// ---- mma.sync / ldmatrix / cp.async helpers (baseline sm_80+ ISA) ---------
__device__ __forceinline__ uint32_t smem_u32(const void* p) {
    uint32_t a;
    asm("{ .reg .u64 t; cvta.to.shared.u64 t, %1; cvt.u32.u64 %0, t; }" : "=r"(a) : "l"(p));
    return a;
}
__device__ __forceinline__ void ldsm4(uint32_t& r0, uint32_t& r1, uint32_t& r2,
                                      uint32_t& r3, uint32_t addr) {
    asm volatile("ldmatrix.sync.aligned.m8n8.x4.shared.b16 {%0,%1,%2,%3}, [%4];"
                 : "=r"(r0), "=r"(r1), "=r"(r2), "=r"(r3) : "r"(addr));
}
__device__ __forceinline__ void mma16816(float* c, uint32_t a0, uint32_t a1,
                                         uint32_t a2, uint32_t a3,
                                         uint32_t b0, uint32_t b1) {
    asm volatile("mma.sync.aligned.m16n8k16.row.col.f32.bf16.bf16.f32 "
                 "{%0,%1,%2,%3}, {%4,%5,%6,%7}, {%8,%9}, {%0,%1,%2,%3};"
                 : "+f"(c[0]), "+f"(c[1]), "+f"(c[2]), "+f"(c[3])
                 : "r"(a0), "r"(a1), "r"(a2), "r"(a3), "r"(b0), "r"(b1));
}
__device__ __forceinline__ void cpa16(uint32_t dst, const void* src) {
    size_t g = __cvta_generic_to_global(src);
    asm volatile("cp.async.cg.shared.global [%0], [%1], 16;" :: "r"(dst), "l"(g) : "memory");
}
#define CPA_COMMIT() asm volatile("cp.async.commit_group;" ::: "memory")
#define CPA_WAIT(n)  asm volatile("cp.async.wait_group %0;" :: "n"(n) : "memory")

__device__ __forceinline__ unsigned short bfbits(__nv_bfloat16 h) {
    return *reinterpret_cast<unsigned short*>(&h);
}
__device__ __forceinline__ unsigned pack_hi(float a, float b) {
    __nv_bfloat16 h0 = __float2bfloat16(a), h1 = __float2bfloat16(b);
    return (unsigned)bfbits(h0) | ((unsigned)bfbits(h1) << 16);
}
__device__ __forceinline__ unsigned pack_lo(float a, float b) {
    __nv_bfloat16 h0 = __float2bfloat16(a), h1 = __float2bfloat16(b);
    __nv_bfloat16 l0 = __float2bfloat16(a - __bfloat162float(h0));
    __nv_bfloat16 l1 = __float2bfloat16(b - __bfloat162float(h1));
    return (unsigned)bfbits(l0) | ((unsigned)bfbits(l1) << 16);
}

// ---------------------------------------------------------------------------
// Prep kernels: split xs / Wx / Wh into bf16 hi+lo
// ---------------------------------------------------------------------------
__global__ void __launch_bounds__(256) xsplit(const float* __restrict__ xs) {
    size_t i4 = ((size_t)blockIdx.x * 256 + threadIdx.x) * 4;
    float4 v = *reinterpret_cast<const float4*>(xs + i4);
    *reinterpret_cast<uint2*>(g_xh + i4) =
        make_uint2(pack_hi(v.x, v.y), pack_hi(v.z, v.w));
    *reinterpret_cast<uint2*>(g_xl + i4) =
        make_uint2(pack_lo(v.x, v.y), pack_lo(v.z, v.w));
}
__global__ void __launch_bounds__(256) w_prep(const float* __restrict__ W) {
    int idx = blockIdx.x * 256 + threadIdx.x;       // 0 .. 2^20-1
    int n = idx >> 10, k = idx & 1023;
    float wx = W[(size_t)n * WSTRIDE + k];
    __nv_bfloat16 xh = __float2bfloat16(wx);
    g_wxh[idx] = bfbits(xh);
    g_wxl[idx] = bfbits(__float2bfloat16(wx - __bfloat162float(xh)));
    float wh = W[(size_t)n * WSTRIDE + DD + k];
    __nv_bfloat16 hh = __float2bfloat16(wh);
    g_whh[idx] = bfbits(hh);
    g_whl[idx] = bfbits(__float2bfloat16(wh - __bfloat162float(hh)));
}

// ---------------------------------------------------------------------------
// Kernel 1: x_proj HMMA GEMM v2. Grid (8 n-tiles, 1024 m-tiles), 256 threads.
// CTA tile 128m x 128n, K=1024 in 16 chunks of 64, 2-buffer cp.async.
// 8 warps = 2wm x 4wn; warp tile 64m x 32n (mma:ldsm = 4:1).
// ---------------------------------------------------------------------------
#define XS 72                                  // smem row stride (elems)
#define X_RA (128 * XS * 2)                    // 18432 B (one half)
#define X_ABUF (2 * X_RA)                      // hi+lo = 36864
#define X_ATOT (2 * X_ABUF)                    // 2 buffers = 73728
#define X_RB (128 * XS * 2)                    // 18432
#define X_BBUF (2 * X_RB)                      // 36864
#define XP2_SMEM (X_ATOT + 2 * X_BBUF)         // 147456 B

__device__ __forceinline__ void xstage(uint32_t sb, int buf, int gm0, int n0,
                                       int kc, int tid) {
#pragma unroll
    for (int q = 0; q < 4; q++) {
        int i = tid + q * 256;                  // 0..1023
        int row = i >> 3, ko = (i & 7) * 8;
        size_t asrc = (size_t)(gm0 + row) * 1024 + kc + ko;
        uint32_t adst = sb + buf * X_ABUF + (uint32_t)((row * XS + ko) * 2);
        cpa16(adst, g_xh + asrc);
        cpa16(adst + X_RA, g_xl + asrc);
        size_t bsrc = (size_t)(n0 + row) * 1024 + kc + ko;
        uint32_t bdst = sb + X_ATOT + buf * X_BBUF + (uint32_t)((row * XS + ko) * 2);
        cpa16(bdst, g_wxh + bsrc);
        cpa16(bdst + X_RB, g_wxl + bsrc);
    }
}

__global__ void __launch_bounds__(256, 1)
xproj_hmma(const float* __restrict__ bias) {
    extern __shared__ __align__(16) char smem[];
    const uint32_t sb = smem_u32(smem);
    const int tid  = threadIdx.x;
    const int wid  = tid >> 5;
    const int lane = tid & 31;
    const int n0  = blockIdx.x * 128;
    const int gm0 = blockIdx.y * 128;
    const int wm = wid >> 2;                   // 0..1 (64m each)
    const int wn = wid & 3;                    // 0..3 (32n each)
    const int gid = lane >> 2, tig = lane & 3;

    uint32_t a_off[4], b_off[2];
#pragma unroll
    for (int mt = 0; mt < 4; mt++)
        a_off[mt] = (uint32_t)(((wm * 64 + mt * 16 + (lane & 7) + ((lane >> 3) & 1) * 8) * XS
                                + (lane >> 4) * 8) * 2);
#pragma unroll
    for (int nt = 0; nt < 2; nt++)
        b_off[nt] = (uint32_t)(((wn * 32 + nt * 16 + (lane & 7) + (lane >> 4) * 8) * XS
                                + ((lane >> 3) & 1) * 8) * 2);

    float acc[4][4][4];
#pragma unroll
    for (int i = 0; i < 4; i++)
#pragma unroll
        for (int j = 0; j < 4; j++)
#pragma unroll
            for (int q = 0; q < 4; q++) acc[i][j][q] = 0.0f;

    xstage(sb, 0, gm0, n0, 0, tid);  CPA_COMMIT();
    xstage(sb, 1, gm0, n0, 64, tid); CPA_COMMIT();

#pragma unroll 1
    for (int c = 0; c < 16; c++) {
        CPA_WAIT(1);
        __syncthreads();

        const uint32_t ab = sb + (c & 1) * X_ABUF;
        const uint32_t bb = sb + X_ATOT + (c & 1) * X_BBUF;
#pragma unroll
        for (int ks = 0; ks < 4; ks++) {
            uint32_t AH[4][4], AL[4][4];
#pragma unroll
            for (int mt = 0; mt < 4; mt++) {
                ldsm4(AH[mt][0], AH[mt][1], AH[mt][2], AH[mt][3], ab + a_off[mt] + ks * 32);
                ldsm4(AL[mt][0], AL[mt][1], AL[mt][2], AL[mt][3],
                      ab + X_RA + a_off[mt] + ks * 32);
            }
#pragma unroll
            for (int nt = 0; nt < 2; nt++) {
                uint32_t bh0, bh1, bh2, bh3, bl0, bl1, bl2, bl3;
                ldsm4(bh0, bh1, bh2, bh3, bb + b_off[nt] + ks * 32);
                ldsm4(bl0, bl1, bl2, bl3, bb + X_RB + b_off[nt] + ks * 32);
#pragma unroll
                for (int mt = 0; mt < 4; mt++) {
                    mma16816(acc[mt][nt * 2 + 0], AH[mt][0], AH[mt][1], AH[mt][2], AH[mt][3], bh0, bh1);
                    mma16816(acc[mt][nt * 2 + 1], AH[mt][0], AH[mt][1], AH[mt][2], AH[mt][3], bh2, bh3);
                    mma16816(acc[mt][nt * 2 + 0], AH[mt][0], AH[mt][1], AH[mt][2], AH[mt][3], bl0, bl1);
                    mma16816(acc[mt][nt * 2 + 1], AH[mt][0], AH[mt][1], AH[mt][2], AH[mt][3], bl2, bl3);
                    mma16816(acc[mt][nt * 2 + 0], AL[mt][0], AL[mt][1], AL[mt][2], AL[mt][3], bh0, bh1);
                    mma16816(acc[mt][nt * 2 + 1], AL[mt][0], AL[mt][1], AL[mt][2], AL[mt][3], bh2, bh3);
                }
            }
        }
        __syncthreads();                       // all reads done before restage
        if (c + 2 < 16) xstage(sb, c & 1, gm0, n0, (c + 2) * 64, tid);
        CPA_COMMIT();
    }

    // epilogue: + bias, remap row (b*T + t) -> x_proj[t][b][:]
    float2 bias2[4];
#pragma unroll
    for (int nq = 0; nq < 4; nq++) {
        int cn = n0 + wn * 32 + (nq >> 1) * 16 + (nq & 1) * 8 + tig * 2;
        bias2[nq] = *reinterpret_cast<const float2*>(bias + cn);
    }
#pragma unroll
    for (int mt = 0; mt < 4; mt++) {
#pragma unroll
        for (int half = 0; half < 2; half++) {
            int gm = gm0 + wm * 64 + mt * 16 + gid + half * 8;
            int b_idx = gm >> 9, tq = gm & 511;
            float* orow = g_xproj + ((size_t)tq * BB + b_idx) * HH;
#pragma unroll
            for (int nq = 0; nq < 4; nq++) {
                int cn = n0 + wn * 32 + (nq >> 1) * 16 + (nq & 1) * 8 + tig * 2;
                *reinterpret_cast<float2*>(orow + cn) =
                    make_float2(acc[mt][nq][half * 2 + 0] + bias2[nq].x,
                                acc[mt][nq][half * 2 + 1] + bias2[nq].y);
            }
        }
    }
}

// ---------------------------------------------------------------------------
// Kernel 2: persistent HMMA recurrence (cp.async 4-buffer A pipeline,
// band barriers, xp prefetched into smem). Grid (32 ni, 4 mi) = 128 CTAs.
// ---------------------------------------------------------------------------
#define RB_STRIDE 1032
#define RB_SIZE   (32 * RB_STRIDE * 2)      // 66048 B
#define RA_STRIDE 72
#define RA_SIZE   (64 * RA_STRIDE * 2)      // 9216 B
#define A_OFF     (2 * RB_SIZE)             // 132096
#define A_BUFSZ   (2 * RA_SIZE)             // 18432
#define XP_OFF    (A_OFF + 4 * A_BUFSZ)     // 205824
#define XP_STRIDE 36                        // fp32 elems per row (16B-aligned)
#define RC_SMEM   (XP_OFF + 64 * XP_STRIDE * 4)   // 215040 B

__device__ __forceinline__ void stage_A(uint32_t sb, int par, int m0, int kc,
                                        int buf, int tid) {
    const unsigned short* sh = g_hh[par];
    const unsigned short* sl = g_hl[par];
#pragma unroll
    for (int q = 0; q < 2; q++) {
        int i = tid + q * 256;
        int row = i >> 3, ko = (i & 7) * 8;
        size_t src = (size_t)(m0 + row) * HH + kc + ko;
        uint32_t dst = sb + A_OFF + buf * A_BUFSZ + (uint32_t)((row * RA_STRIDE + ko) * 2);
        cpa16(dst, sh + src);
        cpa16(dst + RA_SIZE, sl + src);
    }
}

__global__ void __launch_bounds__(256, 1)
recur_hmma(float* __restrict__ out, int copies) {
    extern __shared__ __align__(16) char smem[];
    const uint32_t sb = smem_u32(smem);
    const int tid  = threadIdx.x;
    const int wid  = tid >> 5;
    const int lane = tid & 31;
    const int ni = blockIdx.x;              // 0..31
    const int mi = blockIdx.y;              // 0..3
    const int m0 = mi * 64;
    const int n0 = ni * 32;
    const int wm = wid >> 1, wn = wid & 1;
    const int gid = lane >> 2, tig = lane & 3;
    unsigned* ctr = &g_barM[mi * 32];

    // ---- stage resident Wh slice (rows [n0,+32), hi/lo) -------------------
#pragma unroll
    for (int q = 0; q < 16; q++) {
        int i = tid + q * 256;
        int row = i >> 7, ko = (i & 127) * 8;
        size_t src = (size_t)(n0 + row) * 1024 + ko;
        uint4 vh = *reinterpret_cast<const uint4*>(g_whh + src);
        *reinterpret_cast<uint4*>(smem + (row * RB_STRIDE + ko) * 2) = vh;
        uint4 vl = *reinterpret_cast<const uint4*>(g_whl + src);
        *reinterpret_cast<uint4*>(smem + RB_SIZE + (row * RB_STRIDE + ko) * 2) = vl;
    }

    // ---- Step 0: h0 = 0 -> h[0] = split(tanh(x_proj[0])) on own tile ------
#pragma unroll
    for (int q = 0; q < 2; q++) {
        int i = tid + q * 256;
        int row = i >> 3, c4 = (i & 7) * 4;
        size_t off = (size_t)(m0 + row) * HH + n0 + c4;
        float4 v = __ldcs(reinterpret_cast<const float4*>(g_xproj + off));
        float o[4] = {tanhf(v.x), tanhf(v.y), tanhf(v.z), tanhf(v.w)};
        *reinterpret_cast<uint2*>(&g_hh[0][off]) =
            make_uint2(pack_hi(o[0], o[1]), pack_hi(o[2], o[3]));
        *reinterpret_cast<uint2*>(&g_hl[0][off]) =
            make_uint2(pack_lo(o[0], o[1]), pack_lo(o[2], o[3]));
    }

    // per-lane ldmatrix addresses (warp tile 16m x 16n)
    const int a_row = (lane & 7) + ((lane >> 3) & 1) * 8 + wm * 16;
    const uint32_t a_off = (uint32_t)((a_row * RA_STRIDE + (lane >> 4) * 8) * 2);
    const int b_row = (lane & 7) + (lane >> 4) * 8 + wn * 16;
    const uint32_t b_off = (uint32_t)((b_row * RB_STRIDE + ((lane >> 3) & 1) * 8) * 2);

    for (int t = 1; t < TT; t++) {
        // band barrier over 32 CTAs (monotone counter, bounded spin)
        __syncthreads();
        if (tid == 0) {
            __threadfence();
            atomicAdd(ctr, 1u);
            unsigned tgt = (unsigned)t * 32u;
            for (int it = 0; it < (1 << 18); ++it) {
                if (*((volatile unsigned*)ctr) >= tgt) break;
                __nanosleep(64);
            }
            __threadfence();
        }
        __syncthreads();

        const int par = (t - 1) & 1;
        float acc[2][4];
#pragma unroll
        for (int i = 0; i < 2; i++)
#pragma unroll
            for (int j = 0; j < 4; j++) acc[i][j] = 0.0f;

        // xp prefetch (64m x 32n fp32) bundled into chunk-0's commit group
        {
            const float* xpt = g_xproj + (size_t)t * BH;
#pragma unroll
            for (int q = 0; q < 2; q++) {
                int i = tid + q * 256;              // 0..511
                int row = i >> 3, c4 = (i & 7) * 4;
                cpa16(sb + XP_OFF + (uint32_t)((row * XP_STRIDE + c4) * 4),
                      xpt + (size_t)(m0 + row) * HH + n0 + c4);
            }
        }
        stage_A(sb, par, m0, 0,   0, tid); CPA_COMMIT();
        stage_A(sb, par, m0, 64,  1, tid); CPA_COMMIT();
        stage_A(sb, par, m0, 128, 2, tid); CPA_COMMIT();

#pragma unroll 1
        for (int c = 0; c < 16; c++) {
            CPA_WAIT(2);
            __syncthreads();
            if (c + 3 < 16) stage_A(sb, par, m0, (c + 3) * 64, (c + 3) & 3, tid);
            CPA_COMMIT();

            const uint32_t ab = sb + A_OFF + (c & 3) * A_BUFSZ;
            const uint32_t bkofs = (uint32_t)(c * 64 * 2);
#pragma unroll
            for (int ks = 0; ks < 4; ks++) {
                uint32_t ah0, ah1, ah2, ah3, al0, al1, al2, al3;
                uint32_t bh0, bh1, bh2, bh3, bl0, bl1, bl2, bl3;
                ldsm4(ah0, ah1, ah2, ah3, ab + a_off + ks * 32);
                ldsm4(al0, al1, al2, al3, ab + RA_SIZE + a_off + ks * 32);
                ldsm4(bh0, bh1, bh2, bh3, sb + b_off + bkofs + ks * 32);
                ldsm4(bl0, bl1, bl2, bl3, sb + RB_SIZE + b_off + bkofs + ks * 32);
                mma16816(acc[0], ah0, ah1, ah2, ah3, bh0, bh1);
                mma16816(acc[1], ah0, ah1, ah2, ah3, bh2, bh3);
                mma16816(acc[0], ah0, ah1, ah2, ah3, bl0, bl1);
                mma16816(acc[1], ah0, ah1, ah2, ah3, bl2, bl3);
                mma16816(acc[0], al0, al1, al2, al3, bh0, bh1);
                mma16816(acc[1], al0, al1, al2, al3, bh2, bh3);
            }
        }

        // ---- epilogue: acc + xp(smem) -> tanh -> split -> h (or out) ------
        {
            const int wpar = t & 1;
#pragma unroll
            for (int half = 0; half < 2; half++) {
                const int lr = wm * 16 + gid + half * 8;      // local row 0..63
                const int r = m0 + lr;
#pragma unroll
                for (int nt = 0; nt < 2; nt++) {
                    const int lc = wn * 16 + nt * 8 + tig * 2; // local col 0..31
                    const size_t off = (size_t)r * HH + n0 + lc;
                    float2 x = *reinterpret_cast<const float2*>(
                        smem + XP_OFF + (lr * XP_STRIDE + lc) * 4);
                    float o0 = tanhf(acc[nt][half * 2 + 0] + x.x);
                    float o1 = tanhf(acc[nt][half * 2 + 1] + x.y);
                    if (t == TT - 1) {
                        for (int cc = 0; cc < copies; cc++)
                            *reinterpret_cast<float2*>(out + (size_t)cc * BH + off) =
                                make_float2(o0, o1);
                    } else {
                        *reinterpret_cast<unsigned*>(&g_hh[wpar][off]) = pack_hi(o0, o1);
                        *reinterpret_cast<unsigned*>(&g_hl[wpar][off]) = pack_lo(o0, o1);
                    }
                }
            }
        }
    }

    // ---- exit: band-local barrier + protected, bounded counter reset ------
    __syncthreads();
    if (tid == 0) {
        __threadfence();
        atomicAdd(ctr, 1u);
        if (ni == 0) {
            for (int it = 0; it < (1 << 20); ++it) {
                if (*((volatile unsigned*)ctr) >= (unsigned)TT * 32u) break;
                __nanosleep(64);
            }
            atomicExch(ctr, 0u);
        }
    }
}

// ---------------------------------------------------------------------------
extern "C" void kernel_launch(void* const* d_in, const int* in_sizes, int n_in,
                              void* d_out, int out_size) {
    const float* xs = nullptr; const float* W = nullptr; const float* b = nullptr;
    for (int i = 0; i < n_in; i++) {
        if (in_sizes[i] == MTOT * DD)            xs = (const float*)d_in[i];
        else if (in_sizes[i] == HH * WSTRIDE)    W  = (const float*)d_in[i];
        else if (in_sizes[i] == HH)              b  = (const float*)d_in[i];
    }
    float* out = (float*)d_out;
    int copies = out_size / BH;
    if (copies < 1) copies = 1;
    if (copies > 2) copies = 2;

    static bool configured = false;
    if (!configured) {
        cudaFuncSetAttribute(xproj_hmma,
                             cudaFuncAttributeMaxDynamicSharedMemorySize, XP2_SMEM);
        cudaFuncSetAttribute(recur_hmma,
                             cudaFuncAttributeMaxDynamicSharedMemorySize, RC_SMEM);
        configured = true;
    }

    xsplit<<<131072, 256>>>(xs);
    w_prep<<<4096, 256>>>(W);
    xproj_hmma<<<dim3(8, 1024), 256, XP2_SMEM>>>(b);
    recur_hmma<<<dim3(32, 4), 256, RC_SMEM>>>(out, copies);
}